// round 13
// baseline (speedup 1.0000x reference)
#include <cuda_runtime.h>
#include <cuda_bf16.h>
#include <cstdint>

#define B_ 8
#define T_ 2048
#define C_ 768
#define H_ 64
#define BT_ (B_*T_)
#define NQT 32           // number of 64-query tiles per batch

// Scratch (device globals — no allocation).
__device__ float g_Q[BT_*H_];
__device__ float g_K[BT_*H_];
__device__ float g_V[BT_*H_];
__device__ uint32_t g_Whi[192*384];   // fused W (K,Q,V rows), packed bf16x2 hi
__device__ uint32_t g_Wlo[192*384];   // packed bf16x2 lo (residue)

// ---------------------------------------------------------------------------
// helpers
// ---------------------------------------------------------------------------
__device__ __forceinline__ void mma_bf16(float* d, const uint32_t* a, const uint32_t* b) {
    asm volatile(
        "mma.sync.aligned.m16n8k16.row.col.f32.bf16.bf16.f32 "
        "{%0,%1,%2,%3}, {%4,%5,%6,%7}, {%8,%9}, {%0,%1,%2,%3};"
        : "+f"(d[0]), "+f"(d[1]), "+f"(d[2]), "+f"(d[3])
        : "r"(a[0]), "r"(a[1]), "r"(a[2]), "r"(a[3]), "r"(b[0]), "r"(b[1]));
}

// pack (a,b) into bf16x2 (a in low half); residues packed into lo.
__device__ __forceinline__ uint32_t pack_hilo(float a, float b, uint32_t& lo) {
    __nv_bfloat162 h = __floats2bfloat162_rn(a, b);
    float ha = __bfloat162float(h.x), hb = __bfloat162float(h.y);
    __nv_bfloat162 l = __floats2bfloat162_rn(a - ha, b - hb);
    lo = *reinterpret_cast<uint32_t*>(&l);
    return *reinterpret_cast<uint32_t*>(&h);
}

// ---------------------------------------------------------------------------
// One-shot W conversion: Wk/Wq/Wv [64][768] fp32 -> g_Whi/g_Wlo [192][384].
// Fused row r: 0-63 = Wk, 64-127 = Wq, 128-191 = Wv.
// ---------------------------------------------------------------------------
__global__ __launch_bounds__(256) void convert_w_kernel(
    const float* __restrict__ Wk, const float* __restrict__ Wq,
    const float* __restrict__ Wv)
{
    const int idx = blockIdx.x * 256 + threadIdx.x;   // pair index
    if (idx >= 192*384) return;
    const int r  = idx / 384;
    const int pc = idx % 384;
    const float* W = (r < 64) ? Wk : (r < 128) ? Wq : Wv;
    const int wr = r & 63;
    float2 f = *(const float2*)&W[(size_t)wr * C_ + 2*pc];
    uint32_t lo;
    g_Whi[idx] = pack_hilo(f.x, f.y, lo);
    g_Wlo[idx] = lo;
}

// ---------------------------------------------------------------------------
// Fused QKV projection — bf16 m16n8k16 hi/lo split, one GEMM with N=192.
// out[m, n] = sum_c x[m,c] * Wfused[n,c];  n 0-63 -> g_K, 64-127 -> g_Q,
// 128-191 -> g_V.  M=16384, K=768.
// CTA: 256 threads / 8 warps; 128-row x 192-col tile; warp owns 16 rows.
// x staged+converted ONCE per tile; W copied pre-packed from gmem (no cvt).
// Pitch 20 (>=16 cols; 20*gid+tig mod 32 hits all banks -> conflict-free).
// ---------------------------------------------------------------------------
#define KCH 32
#define QP 20

__global__ __launch_bounds__(256) void qkv_mma_kernel(const float* __restrict__ x)
{
    extern __shared__ uint32_t qsm[];
    uint32_t* Ahi = qsm;                  // 128*20
    uint32_t* Alo = Ahi + 128*QP;         // 128*20
    uint32_t* Bhi = Alo + 128*QP;         // 192*20
    uint32_t* Blo = Bhi + 192*QP;         // 192*20

    const int tid  = threadIdx.x;
    const int w    = tid >> 5;            // 0..7
    const int lane = tid & 31;
    const int gid  = lane >> 2;
    const int tig  = lane & 3;
    const int w16  = w * 16;
    const int m0   = blockIdx.x * 128;

    const int lrow = tid >> 3;            // 0..31 (x staging row group)
    const int lcol = (tid & 7) << 2;      // 0,4,...,28 (float col)
    const int pcol = lcol >> 1;           // packed col base

    float d[24][4] = {};

    for (int kc0 = 0; kc0 < C_; kc0 += KCH) {
        // ---- load x (4 rows/thread) and packed W (12 words/thread) ----
        float4 xa[4];
        #pragma unroll
        for (int i = 0; i < 4; i++)
            xa[i] = *(const float4*)&x[(size_t)(m0 + lrow + 32*i) * C_ + kc0 + lcol];
        uint32_t wh[12], wl[12];
        const int kb = kc0 >> 1;          // packed-k base in W
        #pragma unroll
        for (int i = 0; i < 12; i++) {
            const int idx = tid + 256*i;  // 0..3071 over 192 rows x 16 cols
            const int r = idx >> 4, c = idx & 15;
            wh[i] = g_Whi[r*384 + kb + c];
            wl[i] = g_Wlo[r*384 + kb + c];
        }

        __syncthreads();   // previous chunk's compute done reading smem

        #pragma unroll
        for (int i = 0; i < 4; i++) {
            const int base = (lrow + 32*i) * QP + pcol;
            uint32_t lo;
            Ahi[base    ] = pack_hilo(xa[i].x, xa[i].y, lo);  Alo[base    ] = lo;
            Ahi[base + 1] = pack_hilo(xa[i].z, xa[i].w, lo);  Alo[base + 1] = lo;
        }
        #pragma unroll
        for (int i = 0; i < 12; i++) {
            const int idx = tid + 256*i;
            const int r = idx >> 4, c = idx & 15;
            Bhi[r*QP + c] = wh[i];
            Blo[r*QP + c] = wl[i];
        }
        __syncthreads();

        // ---- compute: 2 k16-steps x 24 ntiles x 3 MMAs ----
        #pragma unroll
        for (int ks = 0; ks < 2; ks++) {
            const int cb = ks * 8;

            uint32_t ah[4], al[4];
            ah[0] = Ahi[(w16 + gid    )*QP + cb + tig    ];
            ah[1] = Ahi[(w16 + gid + 8)*QP + cb + tig    ];
            ah[2] = Ahi[(w16 + gid    )*QP + cb + tig + 4];
            ah[3] = Ahi[(w16 + gid + 8)*QP + cb + tig + 4];
            al[0] = Alo[(w16 + gid    )*QP + cb + tig    ];
            al[1] = Alo[(w16 + gid + 8)*QP + cb + tig    ];
            al[2] = Alo[(w16 + gid    )*QP + cb + tig + 4];
            al[3] = Alo[(w16 + gid + 8)*QP + cb + tig + 4];

            #pragma unroll
            for (int nt = 0; nt < 24; nt++) {
                const int br = (nt*8 + gid)*QP + cb + tig;
                uint32_t bh[2] = { Bhi[br], Bhi[br + 4] };
                uint32_t bl[2] = { Blo[br], Blo[br + 4] };
                mma_bf16(d[nt], ah, bh);   // hi*hi
                mma_bf16(d[nt], ah, bl);   // hi*lo
                mma_bf16(d[nt], al, bh);   // lo*hi
            }
        }
    }

    // ---- epilogue: route nt blocks to g_K / g_Q / g_V ----
    const int r0 = m0 + w16 + gid;
    #pragma unroll
    for (int nt = 0; nt < 24; nt++) {
        float* out = (nt < 8) ? g_K : (nt < 16) ? g_Q : g_V;
        const int c0 = (nt & 7)*8 + 2*tig;
        *(float2*)&out[(size_t)r0      * H_ + c0] = make_float2(d[nt][0], d[nt][1]);
        *(float2*)&out[(size_t)(r0+8) * H_ + c0] = make_float2(d[nt][2], d[nt][3]);
    }
}

// ---------------------------------------------------------------------------
// Flash attention on tensor cores — bf16 m16n8k16 hi/lo split (unchanged R11).
// ---------------------------------------------------------------------------
#define KPITCH 36
#define VPITCH 72
#define GWORDS (2*64*KPITCH + 2*32*VPITCH)   // 9216 words per group

#define BAR_SYNC(id) asm volatile("bar.sync %0, %1;" :: "r"(id), "r"(128) : "memory")

__global__ __launch_bounds__(256) void attn_mma_kernel(float* __restrict__ out)
{
    extern __shared__ uint32_t shb[];

    const int b    = blockIdx.y;
    const int p    = blockIdx.x;
    const int tid  = threadIdx.x;
    const int w    = tid >> 5;
    const int g    = w >> 2;            // warp group 0/1
    const int wg   = w & 3;             // warp within group
    const int lane = tid & 31;
    const int gid  = lane >> 2;
    const int tig  = lane & 3;
    const int w16  = wg * 16;
    const int ltid = tid & 127;

    const int krow = ltid >> 1;            // 0..63 (K row)
    const int kcb  = (ltid & 1) * 32;      // col block 0/32 (h)
    const int vkp  = ltid >> 2;            // 0..31 (V key-pair row)
    const int vcb  = (ltid & 3) * 16;      // h block 0/16/32/48

    uint32_t* Khi = shb + g*GWORDS;        // 64*36
    uint32_t* Klo = Khi + 64*KPITCH;       // 64*36
    uint32_t* Vhi = Klo + 64*KPITCH;       // 32*72
    uint32_t* Vlo = Vhi + 32*VPITCH;       // 32*72

    float* Osm = (float*)(shb + GWORDS);   // 64 x 66 (in group 1's dead K bufs)
    float* Mm  = Osm + 64*66;              // 64
    float* Lm  = Mm + 64;                  // 64

    for (int pick = 0; pick < 2; pick++) {
        const int qtile = pick ? (NQT - 1 - p) : p;

        const float* Qg = g_Q + (size_t)(b*T_ + qtile*64 + w16) * H_;
        uint32_t qh[4][4], ql[4][4];
        #pragma unroll
        for (int ks = 0; ks < 4; ks++) {
            float2 f0 = *(const float2*)&Qg[ gid     *H_ + ks*16 + 2*tig    ];
            float2 f1 = *(const float2*)&Qg[(gid + 8)*H_ + ks*16 + 2*tig    ];
            float2 f2 = *(const float2*)&Qg[ gid     *H_ + ks*16 + 2*tig + 8];
            float2 f3 = *(const float2*)&Qg[(gid + 8)*H_ + ks*16 + 2*tig + 8];
            qh[ks][0] = pack_hilo(f0.x, f0.y, ql[ks][0]);
            qh[ks][1] = pack_hilo(f1.x, f1.y, ql[ks][1]);
            qh[ks][2] = pack_hilo(f2.x, f2.y, ql[ks][2]);
            qh[ks][3] = pack_hilo(f3.x, f3.y, ql[ks][3]);
        }

        float o[8][4] = {};
        float mst[2] = {-1e30f, -1e30f};
        float lst[2] = {0.0f, 0.0f};

        for (int kt = g; kt <= qtile; kt += 2) {
            const float* Kg = g_K + (size_t)(b*T_ + kt*64) * H_;
            const float* Vg = g_V + (size_t)(b*T_ + kt*64) * H_;
            float4 kf[8];
            #pragma unroll
            for (int i = 0; i < 8; i++)
                kf[i] = *(const float4*)&Kg[krow*H_ + kcb + 4*i];
            float4 va[4], vb[4];
            #pragma unroll
            for (int i = 0; i < 4; i++) {
                va[i] = *(const float4*)&Vg[(2*vkp    )*H_ + vcb + 4*i];
                vb[i] = *(const float4*)&Vg[(2*vkp + 1)*H_ + vcb + 4*i];
            }
            BAR_SYNC(g+1);
            #pragma unroll
            for (int i = 0; i < 8; i++) {
                const int c = (kcb >> 1) + 2*i;
                uint32_t lo;
                Khi[krow*KPITCH + c    ] = pack_hilo(kf[i].x, kf[i].y, lo);
                Klo[krow*KPITCH + c    ] = lo;
                Khi[krow*KPITCH + c + 1] = pack_hilo(kf[i].z, kf[i].w, lo);
                Klo[krow*KPITCH + c + 1] = lo;
            }
            #pragma unroll
            for (int i = 0; i < 4; i++) {
                const float* pa = (const float*)&va[i];
                const float* pb = (const float*)&vb[i];
                #pragma unroll
                for (int e = 0; e < 4; e++) {
                    uint32_t lo;
                    Vhi[vkp*VPITCH + vcb + 4*i + e] = pack_hilo(pa[e], pb[e], lo);
                    Vlo[vkp*VPITCH + vcb + 4*i + e] = lo;
                }
            }
            BAR_SYNC(g+1);

            float s[8][4] = {};
            #pragma unroll
            for (int ks = 0; ks < 4; ks++) {
                #pragma unroll
                for (int nt = 0; nt < 8; nt++) {
                    const int kr = (nt*8 + gid)*KPITCH + ks*8 + tig;
                    uint32_t bh[2] = { Khi[kr], Khi[kr + 4] };
                    uint32_t bl[2] = { Klo[kr], Klo[kr + 4] };
                    mma_bf16(s[nt], qh[ks], bh);
                    mma_bf16(s[nt], qh[ks], bl);
                    mma_bf16(s[nt], ql[ks], bh);
                }
            }

            if (kt == qtile) {
                #pragma unroll
                for (int nt = 0; nt < 8; nt++) {
                    const int c0 = nt*8 + 2*tig;
                    if (c0     > w16 + gid    ) s[nt][0] = -1e30f;
                    if (c0 + 1 > w16 + gid    ) s[nt][1] = -1e30f;
                    if (c0     > w16 + gid + 8) s[nt][2] = -1e30f;
                    if (c0 + 1 > w16 + gid + 8) s[nt][3] = -1e30f;
                }
            }

            float mx0 = -1e30f, mx1 = -1e30f;
            #pragma unroll
            for (int nt = 0; nt < 8; nt++) {
                mx0 = fmaxf(mx0, fmaxf(s[nt][0], s[nt][1]));
                mx1 = fmaxf(mx1, fmaxf(s[nt][2], s[nt][3]));
            }
            mx0 = fmaxf(mx0, __shfl_xor_sync(0xffffffffu, mx0, 1));
            mx0 = fmaxf(mx0, __shfl_xor_sync(0xffffffffu, mx0, 2));
            mx1 = fmaxf(mx1, __shfl_xor_sync(0xffffffffu, mx1, 1));
            mx1 = fmaxf(mx1, __shfl_xor_sync(0xffffffffu, mx1, 2));
            const float mn0 = fmaxf(mst[0], mx0);
            const float mn1 = fmaxf(mst[1], mx1);
            const float sc0 = __expf(mst[0] - mn0);
            const float sc1 = __expf(mst[1] - mn1);

            float sum0 = 0.0f, sum1 = 0.0f;
            uint32_t ph[16], plr[16];
            #pragma unroll
            for (int nt = 0; nt < 8; nt++) {
                float p0 = __expf(s[nt][0] - mn0);
                float p1 = __expf(s[nt][1] - mn0);
                float p2 = __expf(s[nt][2] - mn1);
                float p3 = __expf(s[nt][3] - mn1);
                sum0 += p0 + p1;
                sum1 += p2 + p3;
                ph[2*nt    ] = pack_hilo(p0, p1, plr[2*nt    ]);
                ph[2*nt + 1] = pack_hilo(p2, p3, plr[2*nt + 1]);
            }
            sum0 += __shfl_xor_sync(0xffffffffu, sum0, 1);
            sum0 += __shfl_xor_sync(0xffffffffu, sum0, 2);
            sum1 += __shfl_xor_sync(0xffffffffu, sum1, 1);
            sum1 += __shfl_xor_sync(0xffffffffu, sum1, 2);
            lst[0] = lst[0]*sc0 + sum0;  mst[0] = mn0;
            lst[1] = lst[1]*sc1 + sum1;  mst[1] = mn1;
            #pragma unroll
            for (int nt = 0; nt < 8; nt++) {
                o[nt][0] *= sc0; o[nt][1] *= sc0;
                o[nt][2] *= sc1; o[nt][3] *= sc1;
            }

            #pragma unroll
            for (int ks = 0; ks < 4; ks++) {
                #pragma unroll
                for (int nt = 0; nt < 8; nt++) {
                    const int v0 = (ks*8 + tig)*VPITCH + nt*8 + gid;
                    const int v1 = v0 + 4*VPITCH;
                    uint32_t vh[2] = { Vhi[v0], Vhi[v1] };
                    uint32_t vl[2] = { Vlo[v0], Vlo[v1] };
                    mma_bf16(o[nt], &ph[4*ks],  vh);
                    mma_bf16(o[nt], &ph[4*ks],  vl);
                    mma_bf16(o[nt], &plr[4*ks], vh);
                }
            }
        }

        if (g == 1) {
            #pragma unroll
            for (int nt = 0; nt < 8; nt++) {
                const int c0 = nt*8 + 2*tig;
                *(float2*)&Osm[(w16 + gid    )*66 + c0] = make_float2(o[nt][0], o[nt][1]);
                *(float2*)&Osm[(w16 + gid + 8)*66 + c0] = make_float2(o[nt][2], o[nt][3]);
            }
            Mm[w16 + gid    ] = mst[0];  Lm[w16 + gid    ] = lst[0];
            Mm[w16 + gid + 8] = mst[1];  Lm[w16 + gid + 8] = lst[1];
        }
        __syncthreads();
        if (g == 0) {
            const float m1a = Mm[w16 + gid    ], l1a = Lm[w16 + gid    ];
            const float m1b = Mm[w16 + gid + 8], l1b = Lm[w16 + gid + 8];
            const float mF0 = fmaxf(mst[0], m1a);
            const float mF1 = fmaxf(mst[1], m1b);
            const float a00 = __expf(mst[0] - mF0), a01 = __expf(m1a - mF0);
            const float a10 = __expf(mst[1] - mF1), a11 = __expf(m1b - mF1);
            const float inv0 = 1.0f / (lst[0]*a00 + l1a*a01);
            const float inv1 = 1.0f / (lst[1]*a10 + l1b*a11);
            const size_t r0 = (size_t)(b*T_ + qtile*64 + w16 + gid);
            #pragma unroll
            for (int nt = 0; nt < 8; nt++) {
                const int c0 = nt*8 + 2*tig;
                float2 u0 = *(const float2*)&Osm[(w16 + gid    )*66 + c0];
                float2 u1 = *(const float2*)&Osm[(w16 + gid + 8)*66 + c0];
                *(float2*)&out[ r0      * H_ + c0] =
                    make_float2((o[nt][0]*a00 + u0.x*a01)*inv0,
                                (o[nt][1]*a00 + u0.y*a01)*inv0);
                *(float2*)&out[(r0 + 8) * H_ + c0] =
                    make_float2((o[nt][2]*a10 + u1.x*a11)*inv1,
                                (o[nt][3]*a10 + u1.y*a11)*inv1);
            }
        }
        __syncthreads();
    }
}

// ---------------------------------------------------------------------------
extern "C" void kernel_launch(void* const* d_in, const int* in_sizes, int n_in,
                              void* d_out, int out_size)
{
    const float* x  = (const float*)d_in[0];
    const float* Wk = (const float*)d_in[1];
    const float* Wq = (const float*)d_in[2];
    const float* Wv = (const float*)d_in[3];
    float* out = (float*)d_out;

    const int smem_qkv  = (2*128*QP + 2*192*QP) * (int)sizeof(uint32_t);  // 51200 B
    const int smem_attn = 2 * GWORDS * (int)sizeof(uint32_t);             // 73728 B
    cudaFuncSetAttribute(qkv_mma_kernel, cudaFuncAttributeMaxDynamicSharedMemorySize,
                         smem_qkv);
    cudaFuncSetAttribute(attn_mma_kernel, cudaFuncAttributeMaxDynamicSharedMemorySize,
                         smem_attn);

    convert_w_kernel<<<(192*384 + 255)/256, 256>>>(Wk, Wq, Wv);
    qkv_mma_kernel<<<BT_/128, 256, smem_qkv>>>(x);
    attn_mma_kernel<<<dim3(NQT/2, B_), 256, smem_attn>>>(out);
}

// round 14
// speedup vs baseline: 1.4456x; 1.4456x over previous
#include <cuda_runtime.h>
#include <cuda_bf16.h>
#include <cstdint>

#define B_ 8
#define T_ 2048
#define C_ 768
#define H_ 64
#define BT_ (B_*T_)
#define NQT 32           // number of 64-query tiles per batch

// Scratch (device globals — no allocation).
__device__ float g_Q[BT_*H_];
__device__ float g_K[BT_*H_];
__device__ float g_V[BT_*H_];
__device__ uint32_t g_Whi[192*384];   // fused W (K,Q,V rows), packed bf16x2 hi
__device__ uint32_t g_Wlo[192*384];   // packed bf16x2 lo (residue)

// ---------------------------------------------------------------------------
// helpers
// ---------------------------------------------------------------------------
__device__ __forceinline__ void mma_bf16(float* d, const uint32_t* a, const uint32_t* b) {
    asm volatile(
        "mma.sync.aligned.m16n8k16.row.col.f32.bf16.bf16.f32 "
        "{%0,%1,%2,%3}, {%4,%5,%6,%7}, {%8,%9}, {%0,%1,%2,%3};"
        : "+f"(d[0]), "+f"(d[1]), "+f"(d[2]), "+f"(d[3])
        : "r"(a[0]), "r"(a[1]), "r"(a[2]), "r"(a[3]), "r"(b[0]), "r"(b[1]));
}

// pack (a,b) into bf16x2 (a in low half); residues packed into lo.
__device__ __forceinline__ uint32_t pack_hilo(float a, float b, uint32_t& lo) {
    __nv_bfloat162 h = __floats2bfloat162_rn(a, b);
    float ha = __bfloat162float(h.x), hb = __bfloat162float(h.y);
    __nv_bfloat162 l = __floats2bfloat162_rn(a - ha, b - hb);
    lo = *reinterpret_cast<uint32_t*>(&l);
    return *reinterpret_cast<uint32_t*>(&h);
}

// ---------------------------------------------------------------------------
// One-shot W conversion: Wk/Wq/Wv [64][768] fp32 -> g_Whi/g_Wlo [192][384].
// Fused row r: 0-63 = Wk, 64-127 = Wq, 128-191 = Wv.
// ---------------------------------------------------------------------------
__global__ __launch_bounds__(256) void convert_w_kernel(
    const float* __restrict__ Wk, const float* __restrict__ Wq,
    const float* __restrict__ Wv)
{
    const int idx = blockIdx.x * 256 + threadIdx.x;   // pair index
    if (idx >= 192*384) return;
    const int r  = idx / 384;
    const int pc = idx % 384;
    const float* W = (r < 64) ? Wk : (r < 128) ? Wq : Wv;
    const int wr = r & 63;
    float2 f = *(const float2*)&W[(size_t)wr * C_ + 2*pc];
    uint32_t lo;
    g_Whi[idx] = pack_hilo(f.x, f.y, lo);
    g_Wlo[idx] = lo;
}

// ---------------------------------------------------------------------------
// Fused QKV projection v2 — bf16 m16n8k16 hi/lo split, one GEMM with N=192.
// CTA: 256 threads / 8 warps; 64-row x 192-col tile (48 accum regs/thread).
// Warp (w&3) owns 16 rows; (w>>2) selects 96-col half (nt = 12 per warp).
// x staged+converted ONCE per tile; W copied pre-packed from gmem (no cvt).
// Pitch 20 (20*gid+tig mod 32 hits all banks; 20*96 ≡ 0 mod 32 preserves it).
// ---------------------------------------------------------------------------
#define KCH 32
#define QP 20

__global__ __launch_bounds__(256) void qkv_mma_kernel(const float* __restrict__ x)
{
    extern __shared__ uint32_t qsm[];
    uint32_t* Ahi = qsm;                  // 64*20
    uint32_t* Alo = Ahi + 64*QP;          // 64*20
    uint32_t* Bhi = Alo + 64*QP;          // 192*20
    uint32_t* Blo = Bhi + 192*QP;         // 192*20

    const int tid  = threadIdx.x;
    const int w    = tid >> 5;            // 0..7
    const int lane = tid & 31;
    const int gid  = lane >> 2;
    const int tig  = lane & 3;
    const int mb   = (w & 3) * 16;        // warp's row base in tile
    const int nb   = (w >> 2) * 96;       // warp's col base in tile
    const int m0   = blockIdx.x * 64;

    const int lrow = tid >> 3;            // 0..31 (x staging row group)
    const int lcol = (tid & 7) << 2;      // 0,4,...,28 (float col)
    const int pcol = lcol >> 1;           // packed col base

    float d[12][4] = {};

    for (int kc0 = 0; kc0 < C_; kc0 += KCH) {
        // ---- load x (2 rows/thread) and packed W (12 words/thread) ----
        float4 xa[2];
        xa[0] = *(const float4*)&x[(size_t)(m0 + lrow     ) * C_ + kc0 + lcol];
        xa[1] = *(const float4*)&x[(size_t)(m0 + lrow + 32) * C_ + kc0 + lcol];
        uint32_t wh[12], wl[12];
        const int kb = kc0 >> 1;          // packed-k base in W
        #pragma unroll
        for (int i = 0; i < 12; i++) {
            const int idx = tid + 256*i;  // 0..3071 over 192 rows x 16 cols
            const int r = idx >> 4, c = idx & 15;
            wh[i] = g_Whi[r*384 + kb + c];
            wl[i] = g_Wlo[r*384 + kb + c];
        }

        __syncthreads();   // previous chunk's compute done reading smem

        #pragma unroll
        for (int i = 0; i < 2; i++) {
            const int base = (lrow + 32*i) * QP + pcol;
            uint32_t lo;
            Ahi[base    ] = pack_hilo(xa[i].x, xa[i].y, lo);  Alo[base    ] = lo;
            Ahi[base + 1] = pack_hilo(xa[i].z, xa[i].w, lo);  Alo[base + 1] = lo;
        }
        #pragma unroll
        for (int i = 0; i < 12; i++) {
            const int idx = tid + 256*i;
            const int r = idx >> 4, c = idx & 15;
            Bhi[r*QP + c] = wh[i];
            Blo[r*QP + c] = wl[i];
        }
        __syncthreads();

        // ---- compute: 2 k16-steps x 12 ntiles x 3 MMAs ----
        #pragma unroll
        for (int ks = 0; ks < 2; ks++) {
            const int cb = ks * 8;

            uint32_t ah[4], al[4];
            ah[0] = Ahi[(mb + gid    )*QP + cb + tig    ];
            ah[1] = Ahi[(mb + gid + 8)*QP + cb + tig    ];
            ah[2] = Ahi[(mb + gid    )*QP + cb + tig + 4];
            ah[3] = Ahi[(mb + gid + 8)*QP + cb + tig + 4];
            al[0] = Alo[(mb + gid    )*QP + cb + tig    ];
            al[1] = Alo[(mb + gid + 8)*QP + cb + tig    ];
            al[2] = Alo[(mb + gid    )*QP + cb + tig + 4];
            al[3] = Alo[(mb + gid + 8)*QP + cb + tig + 4];

            #pragma unroll
            for (int nt = 0; nt < 12; nt++) {
                const int br = (nb + nt*8 + gid)*QP + cb + tig;
                uint32_t bh[2] = { Bhi[br], Bhi[br + 4] };
                uint32_t bl[2] = { Blo[br], Blo[br + 4] };
                mma_bf16(d[nt], ah, bh);   // hi*hi
                mma_bf16(d[nt], ah, bl);   // hi*lo
                mma_bf16(d[nt], al, bh);   // lo*hi
            }
        }
    }

    // ---- epilogue: route n blocks to g_K / g_Q / g_V ----
    const int r0 = m0 + mb + gid;
    #pragma unroll
    for (int nt = 0; nt < 12; nt++) {
        const int gc = nb + nt*8;                 // global fused col base
        float* out = (gc < 64) ? g_K : (gc < 128) ? g_Q : g_V;
        const int c0 = (gc & 63) + 2*tig;
        *(float2*)&out[(size_t)r0      * H_ + c0] = make_float2(d[nt][0], d[nt][1]);
        *(float2*)&out[(size_t)(r0+8) * H_ + c0] = make_float2(d[nt][2], d[nt][3]);
    }
}

// ---------------------------------------------------------------------------
// Flash attention on tensor cores — bf16 m16n8k16 hi/lo split (proven R11/R12).
// ---------------------------------------------------------------------------
#define KPITCH 36
#define VPITCH 72
#define GWORDS (2*64*KPITCH + 2*32*VPITCH)   // 9216 words per group

#define BAR_SYNC(id) asm volatile("bar.sync %0, %1;" :: "r"(id), "r"(128) : "memory")

__global__ __launch_bounds__(256) void attn_mma_kernel(float* __restrict__ out)
{
    extern __shared__ uint32_t shb[];

    const int b    = blockIdx.y;
    const int p    = blockIdx.x;
    const int tid  = threadIdx.x;
    const int w    = tid >> 5;
    const int g    = w >> 2;            // warp group 0/1
    const int wg   = w & 3;             // warp within group
    const int lane = tid & 31;
    const int gid  = lane >> 2;
    const int tig  = lane & 3;
    const int w16  = wg * 16;
    const int ltid = tid & 127;

    const int krow = ltid >> 1;            // 0..63 (K row)
    const int kcb  = (ltid & 1) * 32;      // col block 0/32 (h)
    const int vkp  = ltid >> 2;            // 0..31 (V key-pair row)
    const int vcb  = (ltid & 3) * 16;      // h block 0/16/32/48

    uint32_t* Khi = shb + g*GWORDS;        // 64*36
    uint32_t* Klo = Khi + 64*KPITCH;       // 64*36
    uint32_t* Vhi = Klo + 64*KPITCH;       // 32*72
    uint32_t* Vlo = Vhi + 32*VPITCH;       // 32*72

    float* Osm = (float*)(shb + GWORDS);   // 64 x 66 (in group 1's dead K bufs)
    float* Mm  = Osm + 64*66;              // 64
    float* Lm  = Mm + 64;                  // 64

    for (int pick = 0; pick < 2; pick++) {
        const int qtile = pick ? (NQT - 1 - p) : p;

        const float* Qg = g_Q + (size_t)(b*T_ + qtile*64 + w16) * H_;
        uint32_t qh[4][4], ql[4][4];
        #pragma unroll
        for (int ks = 0; ks < 4; ks++) {
            float2 f0 = *(const float2*)&Qg[ gid     *H_ + ks*16 + 2*tig    ];
            float2 f1 = *(const float2*)&Qg[(gid + 8)*H_ + ks*16 + 2*tig    ];
            float2 f2 = *(const float2*)&Qg[ gid     *H_ + ks*16 + 2*tig + 8];
            float2 f3 = *(const float2*)&Qg[(gid + 8)*H_ + ks*16 + 2*tig + 8];
            qh[ks][0] = pack_hilo(f0.x, f0.y, ql[ks][0]);
            qh[ks][1] = pack_hilo(f1.x, f1.y, ql[ks][1]);
            qh[ks][2] = pack_hilo(f2.x, f2.y, ql[ks][2]);
            qh[ks][3] = pack_hilo(f3.x, f3.y, ql[ks][3]);
        }

        float o[8][4] = {};
        float mst[2] = {-1e30f, -1e30f};
        float lst[2] = {0.0f, 0.0f};

        for (int kt = g; kt <= qtile; kt += 2) {
            const float* Kg = g_K + (size_t)(b*T_ + kt*64) * H_;
            const float* Vg = g_V + (size_t)(b*T_ + kt*64) * H_;
            float4 kf[8];
            #pragma unroll
            for (int i = 0; i < 8; i++)
                kf[i] = *(const float4*)&Kg[krow*H_ + kcb + 4*i];
            float4 va[4], vb[4];
            #pragma unroll
            for (int i = 0; i < 4; i++) {
                va[i] = *(const float4*)&Vg[(2*vkp    )*H_ + vcb + 4*i];
                vb[i] = *(const float4*)&Vg[(2*vkp + 1)*H_ + vcb + 4*i];
            }
            BAR_SYNC(g+1);
            #pragma unroll
            for (int i = 0; i < 8; i++) {
                const int c = (kcb >> 1) + 2*i;
                uint32_t lo;
                Khi[krow*KPITCH + c    ] = pack_hilo(kf[i].x, kf[i].y, lo);
                Klo[krow*KPITCH + c    ] = lo;
                Khi[krow*KPITCH + c + 1] = pack_hilo(kf[i].z, kf[i].w, lo);
                Klo[krow*KPITCH + c + 1] = lo;
            }
            #pragma unroll
            for (int i = 0; i < 4; i++) {
                const float* pa = (const float*)&va[i];
                const float* pb = (const float*)&vb[i];
                #pragma unroll
                for (int e = 0; e < 4; e++) {
                    uint32_t lo;
                    Vhi[vkp*VPITCH + vcb + 4*i + e] = pack_hilo(pa[e], pb[e], lo);
                    Vlo[vkp*VPITCH + vcb + 4*i + e] = lo;
                }
            }
            BAR_SYNC(g+1);

            float s[8][4] = {};
            #pragma unroll
            for (int ks = 0; ks < 4; ks++) {
                #pragma unroll
                for (int nt = 0; nt < 8; nt++) {
                    const int kr = (nt*8 + gid)*KPITCH + ks*8 + tig;
                    uint32_t bh[2] = { Khi[kr], Khi[kr + 4] };
                    uint32_t bl[2] = { Klo[kr], Klo[kr + 4] };
                    mma_bf16(s[nt], qh[ks], bh);
                    mma_bf16(s[nt], qh[ks], bl);
                    mma_bf16(s[nt], ql[ks], bh);
                }
            }

            if (kt == qtile) {
                #pragma unroll
                for (int nt = 0; nt < 8; nt++) {
                    const int c0 = nt*8 + 2*tig;
                    if (c0     > w16 + gid    ) s[nt][0] = -1e30f;
                    if (c0 + 1 > w16 + gid    ) s[nt][1] = -1e30f;
                    if (c0     > w16 + gid + 8) s[nt][2] = -1e30f;
                    if (c0 + 1 > w16 + gid + 8) s[nt][3] = -1e30f;
                }
            }

            float mx0 = -1e30f, mx1 = -1e30f;
            #pragma unroll
            for (int nt = 0; nt < 8; nt++) {
                mx0 = fmaxf(mx0, fmaxf(s[nt][0], s[nt][1]));
                mx1 = fmaxf(mx1, fmaxf(s[nt][2], s[nt][3]));
            }
            mx0 = fmaxf(mx0, __shfl_xor_sync(0xffffffffu, mx0, 1));
            mx0 = fmaxf(mx0, __shfl_xor_sync(0xffffffffu, mx0, 2));
            mx1 = fmaxf(mx1, __shfl_xor_sync(0xffffffffu, mx1, 1));
            mx1 = fmaxf(mx1, __shfl_xor_sync(0xffffffffu, mx1, 2));
            const float mn0 = fmaxf(mst[0], mx0);
            const float mn1 = fmaxf(mst[1], mx1);
            const float sc0 = __expf(mst[0] - mn0);
            const float sc1 = __expf(mst[1] - mn1);

            float sum0 = 0.0f, sum1 = 0.0f;
            uint32_t ph[16], plr[16];
            #pragma unroll
            for (int nt = 0; nt < 8; nt++) {
                float p0 = __expf(s[nt][0] - mn0);
                float p1 = __expf(s[nt][1] - mn0);
                float p2 = __expf(s[nt][2] - mn1);
                float p3 = __expf(s[nt][3] - mn1);
                sum0 += p0 + p1;
                sum1 += p2 + p3;
                ph[2*nt    ] = pack_hilo(p0, p1, plr[2*nt    ]);
                ph[2*nt + 1] = pack_hilo(p2, p3, plr[2*nt + 1]);
            }
            sum0 += __shfl_xor_sync(0xffffffffu, sum0, 1);
            sum0 += __shfl_xor_sync(0xffffffffu, sum0, 2);
            sum1 += __shfl_xor_sync(0xffffffffu, sum1, 1);
            sum1 += __shfl_xor_sync(0xffffffffu, sum1, 2);
            lst[0] = lst[0]*sc0 + sum0;  mst[0] = mn0;
            lst[1] = lst[1]*sc1 + sum1;  mst[1] = mn1;
            #pragma unroll
            for (int nt = 0; nt < 8; nt++) {
                o[nt][0] *= sc0; o[nt][1] *= sc0;
                o[nt][2] *= sc1; o[nt][3] *= sc1;
            }

            #pragma unroll
            for (int ks = 0; ks < 4; ks++) {
                #pragma unroll
                for (int nt = 0; nt < 8; nt++) {
                    const int v0 = (ks*8 + tig)*VPITCH + nt*8 + gid;
                    const int v1 = v0 + 4*VPITCH;
                    uint32_t vh[2] = { Vhi[v0], Vhi[v1] };
                    uint32_t vl[2] = { Vlo[v0], Vlo[v1] };
                    mma_bf16(o[nt], &ph[4*ks],  vh);
                    mma_bf16(o[nt], &ph[4*ks],  vl);
                    mma_bf16(o[nt], &plr[4*ks], vh);
                }
            }
        }

        if (g == 1) {
            #pragma unroll
            for (int nt = 0; nt < 8; nt++) {
                const int c0 = nt*8 + 2*tig;
                *(float2*)&Osm[(w16 + gid    )*66 + c0] = make_float2(o[nt][0], o[nt][1]);
                *(float2*)&Osm[(w16 + gid + 8)*66 + c0] = make_float2(o[nt][2], o[nt][3]);
            }
            Mm[w16 + gid    ] = mst[0];  Lm[w16 + gid    ] = lst[0];
            Mm[w16 + gid + 8] = mst[1];  Lm[w16 + gid + 8] = lst[1];
        }
        __syncthreads();
        if (g == 0) {
            const float m1a = Mm[w16 + gid    ], l1a = Lm[w16 + gid    ];
            const float m1b = Mm[w16 + gid + 8], l1b = Lm[w16 + gid + 8];
            const float mF0 = fmaxf(mst[0], m1a);
            const float mF1 = fmaxf(mst[1], m1b);
            const float a00 = __expf(mst[0] - mF0), a01 = __expf(m1a - mF0);
            const float a10 = __expf(mst[1] - mF1), a11 = __expf(m1b - mF1);
            const float inv0 = 1.0f / (lst[0]*a00 + l1a*a01);
            const float inv1 = 1.0f / (lst[1]*a10 + l1b*a11);
            const size_t r0 = (size_t)(b*T_ + qtile*64 + w16 + gid);
            #pragma unroll
            for (int nt = 0; nt < 8; nt++) {
                const int c0 = nt*8 + 2*tig;
                float2 u0 = *(const float2*)&Osm[(w16 + gid    )*66 + c0];
                float2 u1 = *(const float2*)&Osm[(w16 + gid + 8)*66 + c0];
                *(float2*)&out[ r0      * H_ + c0] =
                    make_float2((o[nt][0]*a00 + u0.x*a01)*inv0,
                                (o[nt][1]*a00 + u0.y*a01)*inv0);
                *(float2*)&out[(r0 + 8) * H_ + c0] =
                    make_float2((o[nt][2]*a10 + u1.x*a11)*inv1,
                                (o[nt][3]*a10 + u1.y*a11)*inv1);
            }
        }
        __syncthreads();
    }
}

// ---------------------------------------------------------------------------
extern "C" void kernel_launch(void* const* d_in, const int* in_sizes, int n_in,
                              void* d_out, int out_size)
{
    const float* x  = (const float*)d_in[0];
    const float* Wk = (const float*)d_in[1];
    const float* Wq = (const float*)d_in[2];
    const float* Wv = (const float*)d_in[3];
    float* out = (float*)d_out;

    const int smem_qkv  = (2*64*QP + 2*192*QP) * (int)sizeof(uint32_t);  // 40960 B
    const int smem_attn = 2 * GWORDS * (int)sizeof(uint32_t);            // 73728 B
    cudaFuncSetAttribute(qkv_mma_kernel, cudaFuncAttributeMaxDynamicSharedMemorySize,
                         smem_qkv);
    cudaFuncSetAttribute(attn_mma_kernel, cudaFuncAttributeMaxDynamicSharedMemorySize,
                         smem_attn);

    convert_w_kernel<<<(192*384 + 255)/256, 256>>>(Wk, Wq, Wv);
    qkv_mma_kernel<<<BT_/64, 256, smem_qkv>>>(x);
    attn_mma_kernel<<<dim3(NQT/2, B_), 256, smem_attn>>>(out);
}

// round 15
// speedup vs baseline: 1.5654x; 1.0829x over previous
#include <cuda_runtime.h>
#include <cuda_bf16.h>
#include <cstdint>

#define B_ 8
#define T_ 2048
#define C_ 768
#define H_ 64
#define BT_ (B_*T_)
#define NQT 32           // number of 64-query tiles per batch

// Scratch (device globals — no allocation).
__device__ float g_Q[BT_*H_];
__device__ float g_K[BT_*H_];
__device__ float g_V[BT_*H_];

// ---------------------------------------------------------------------------
// helpers
// ---------------------------------------------------------------------------
__device__ __forceinline__ void mma_bf16(float* d, const uint32_t* a, const uint32_t* b) {
    asm volatile(
        "mma.sync.aligned.m16n8k16.row.col.f32.bf16.bf16.f32 "
        "{%0,%1,%2,%3}, {%4,%5,%6,%7}, {%8,%9}, {%0,%1,%2,%3};"
        : "+f"(d[0]), "+f"(d[1]), "+f"(d[2]), "+f"(d[3])
        : "r"(a[0]), "r"(a[1]), "r"(a[2]), "r"(a[3]), "r"(b[0]), "r"(b[1]));
}

// pack (a,b) into bf16x2 (a in low half); residues packed into lo.
__device__ __forceinline__ uint32_t pack_hilo(float a, float b, uint32_t& lo) {
    __nv_bfloat162 h = __floats2bfloat162_rn(a, b);
    float ha = __bfloat162float(h.x), hb = __bfloat162float(h.y);
    __nv_bfloat162 l = __floats2bfloat162_rn(a - ha, b - hb);
    lo = *reinterpret_cast<uint32_t*>(&l);
    return *reinterpret_cast<uint32_t*>(&h);
}

// ---------------------------------------------------------------------------
// QKV projection — R12 proven kernel (bf16 m16n8k16 hi/lo split, 3 instances).
// out[m,h] = sum_c x[m,c] * W[h,c].  M=16384, N=64, K=768.
// ---------------------------------------------------------------------------
#define KCH 32
#define QP 20

__global__ __launch_bounds__(128) void qkv_mma_kernel(
    const float* __restrict__ x, const float* __restrict__ Wk,
    const float* __restrict__ Wq, const float* __restrict__ Wv)
{
    extern __shared__ uint32_t qsm[];
    uint32_t* Ahi = qsm;                  // 128*20
    uint32_t* Alo = Ahi + 128*QP;         // 128*20
    uint32_t* Bhi = Alo + 128*QP;         // 64*20
    uint32_t* Blo = Bhi + 64*QP;          // 64*20

    const float* W;
    float* out;
    if (blockIdx.y == 0)      { W = Wk; out = g_K; }
    else if (blockIdx.y == 1) { W = Wq; out = g_Q; }
    else                      { W = Wv; out = g_V; }

    const int tid  = threadIdx.x;
    const int wid  = tid >> 5;
    const int lane = tid & 31;
    const int gid  = lane >> 2;
    const int tig  = lane & 3;
    const int m0   = blockIdx.x * 128;

    const int lrow = tid >> 3;            // 0..15
    const int lcol = (tid & 7) << 2;      // 0,4,...,28
    const int pcol = lcol >> 1;

    float d[2][8][4] = {};

    for (int kc0 = 0; kc0 < C_; kc0 += KCH) {
        float4 xa[8], wa[4];
        #pragma unroll
        for (int i = 0; i < 8; i++)
            xa[i] = *(const float4*)&x[(size_t)(m0 + lrow + 16*i) * C_ + kc0 + lcol];
        #pragma unroll
        for (int i = 0; i < 4; i++)
            wa[i] = *(const float4*)&W[(size_t)(lrow + 16*i) * C_ + kc0 + lcol];

        __syncthreads();

        #pragma unroll
        for (int i = 0; i < 8; i++) {
            const int base = (lrow + 16*i) * QP + pcol;
            uint32_t lo;
            Ahi[base    ] = pack_hilo(xa[i].x, xa[i].y, lo);  Alo[base    ] = lo;
            Ahi[base + 1] = pack_hilo(xa[i].z, xa[i].w, lo);  Alo[base + 1] = lo;
        }
        #pragma unroll
        for (int i = 0; i < 4; i++) {
            const int base = (lrow + 16*i) * QP + pcol;
            uint32_t lo;
            Bhi[base    ] = pack_hilo(wa[i].x, wa[i].y, lo);  Blo[base    ] = lo;
            Bhi[base + 1] = pack_hilo(wa[i].z, wa[i].w, lo);  Blo[base + 1] = lo;
        }
        __syncthreads();

        #pragma unroll
        for (int ks = 0; ks < 2; ks++) {
            const int cb = ks * 8;

            uint32_t ah[2][4], al[2][4];
            #pragma unroll
            for (int mt = 0; mt < 2; mt++) {
                const int rw = wid*32 + mt*16;
                ah[mt][0] = Ahi[(rw + gid    )*QP + cb + tig    ];
                ah[mt][1] = Ahi[(rw + gid + 8)*QP + cb + tig    ];
                ah[mt][2] = Ahi[(rw + gid    )*QP + cb + tig + 4];
                ah[mt][3] = Ahi[(rw + gid + 8)*QP + cb + tig + 4];
                al[mt][0] = Alo[(rw + gid    )*QP + cb + tig    ];
                al[mt][1] = Alo[(rw + gid + 8)*QP + cb + tig    ];
                al[mt][2] = Alo[(rw + gid    )*QP + cb + tig + 4];
                al[mt][3] = Alo[(rw + gid + 8)*QP + cb + tig + 4];
            }

            uint32_t bh[8][2], bl[8][2];
            #pragma unroll
            for (int nt = 0; nt < 8; nt++) {
                bh[nt][0] = Bhi[(nt*8 + gid)*QP + cb + tig    ];
                bh[nt][1] = Bhi[(nt*8 + gid)*QP + cb + tig + 4];
                bl[nt][0] = Blo[(nt*8 + gid)*QP + cb + tig    ];
                bl[nt][1] = Blo[(nt*8 + gid)*QP + cb + tig + 4];
            }

            #pragma unroll
            for (int mt = 0; mt < 2; mt++)
                #pragma unroll
                for (int nt = 0; nt < 8; nt++) {
                    mma_bf16(d[mt][nt], ah[mt], bh[nt]);
                    mma_bf16(d[mt][nt], ah[mt], bl[nt]);
                    mma_bf16(d[mt][nt], al[mt], bh[nt]);
                }
        }
    }

    #pragma unroll
    for (int mt = 0; mt < 2; mt++) {
        const int r0 = m0 + wid*32 + mt*16 + gid;
        #pragma unroll
        for (int nt = 0; nt < 8; nt++) {
            const int c0 = nt*8 + 2*tig;
            *(float2*)&out[(size_t)r0      * H_ + c0] = make_float2(d[mt][nt][0], d[mt][nt][1]);
            *(float2*)&out[(size_t)(r0+8) * H_ + c0] = make_float2(d[mt][nt][2], d[mt][nt][3]);
        }
    }
}

// ---------------------------------------------------------------------------
// Flash attention — bf16 m16n8k16 hi/lo split, 128-KEY tiles per iteration.
// Grid (16, 8): CTA (p, b) processes qtiles {p, 31-p}. 256 threads / 8 warps:
// group g handles 128-key tile t ≡ g (mod 2), own K/V smem + named barrier.
// Per iter: stage K[128x64]/V[128x64] (two 64-key sub-batches), S = Q@K^T
// (16 ntiles), mask, softmax max, then interleaved per-k16: exp+pack -> PV.
// K smem: 128 rows x 32 packed cols, pitch 36 (bank 4*gid+tig, all distinct).
// V smem: 64 key-pair rows x 64 cols, pitch 72 (bank 8*tig+gid, all distinct).
// ---------------------------------------------------------------------------
#define KPITCH 36
#define VPITCH 72
#define GWORDS (2*128*KPITCH + 2*64*VPITCH)   // 18432 words per group

#define BAR_SYNC(id) asm volatile("bar.sync %0, %1;" :: "r"(id), "r"(128) : "memory")

__global__ __launch_bounds__(256) void attn_mma_kernel(float* __restrict__ out)
{
    extern __shared__ uint32_t shb[];

    const int b    = blockIdx.y;
    const int p    = blockIdx.x;
    const int tid  = threadIdx.x;
    const int w    = tid >> 5;
    const int g    = w >> 2;            // warp group 0/1
    const int wg   = w & 3;             // warp within group
    const int lane = tid & 31;
    const int gid  = lane >> 2;
    const int tig  = lane & 3;
    const int w16  = wg * 16;
    const int ltid = tid & 127;

    const int krow = ltid >> 1;            // 0..63 (K row within sub-batch)
    const int kcb  = (ltid & 1) * 32;      // h block 0/32
    const int vkp  = ltid >> 2;            // 0..31 (V key-pair row within sub-batch)
    const int vcb  = (ltid & 3) * 16;      // h block 0/16/32/48

    uint32_t* Khi = shb + g*GWORDS;        // 128*36
    uint32_t* Klo = Khi + 128*KPITCH;      // 128*36
    uint32_t* Vhi = Klo + 128*KPITCH;      // 64*72
    uint32_t* Vlo = Vhi + 64*VPITCH;       // 64*72

    // Merge region reuses group 1's K buffers (9216 words, dead after loop).
    float* Osm = (float*)(shb + GWORDS);   // 64 x 66 = 4224
    float* Mm  = Osm + 64*66;              // 64
    float* Lm  = Mm + 64;                  // 64   (4352 < 9216)

    for (int pick = 0; pick < 2; pick++) {
        const int qtile = pick ? (NQT - 1 - p) : p;

        // ---- Q A-fragments (bf16 hi/lo packed pairs), in registers ----
        const float* Qg = g_Q + (size_t)(b*T_ + qtile*64 + w16) * H_;
        uint32_t qh[4][4], ql[4][4];
        #pragma unroll
        for (int ks = 0; ks < 4; ks++) {
            float2 f0 = *(const float2*)&Qg[ gid     *H_ + ks*16 + 2*tig    ];
            float2 f1 = *(const float2*)&Qg[(gid + 8)*H_ + ks*16 + 2*tig    ];
            float2 f2 = *(const float2*)&Qg[ gid     *H_ + ks*16 + 2*tig + 8];
            float2 f3 = *(const float2*)&Qg[(gid + 8)*H_ + ks*16 + 2*tig + 8];
            qh[ks][0] = pack_hilo(f0.x, f0.y, ql[ks][0]);
            qh[ks][1] = pack_hilo(f1.x, f1.y, ql[ks][1]);
            qh[ks][2] = pack_hilo(f2.x, f2.y, ql[ks][2]);
            qh[ks][3] = pack_hilo(f3.x, f3.y, ql[ks][3]);
        }

        float o[8][4] = {};
        float mst[2] = {-1e30f, -1e30f};
        float lst[2] = {0.0f, 0.0f};

        const int tmax = qtile >> 1;
        for (int t = g; t <= tmax; t += 2) {
            const float* Kg = g_K + (size_t)(b*T_ + t*128) * H_;
            const float* Vg = g_V + (size_t)(b*T_ + t*128) * H_;

            // ---- sub-batch 0 loads (K rows 0-63, V pairs 0-31) + K batch 1 ----
            float4 kf[8], va[4], vb[4], kf2[8];
            #pragma unroll
            for (int i = 0; i < 8; i++)
                kf[i]  = *(const float4*)&Kg[ krow      *H_ + kcb + 4*i];
            #pragma unroll
            for (int i = 0; i < 4; i++) {
                va[i] = *(const float4*)&Vg[(2*vkp    )*H_ + vcb + 4*i];
                vb[i] = *(const float4*)&Vg[(2*vkp + 1)*H_ + vcb + 4*i];
            }
            #pragma unroll
            for (int i = 0; i < 8; i++)
                kf2[i] = *(const float4*)&Kg[(krow + 64)*H_ + kcb + 4*i];

            BAR_SYNC(g+1);   // group's prev-iter readers done

            // store K batch 0 + V batch 0
            #pragma unroll
            for (int i = 0; i < 8; i++) {
                const int c = (kcb >> 1) + 2*i;
                uint32_t lo;
                Khi[krow*KPITCH + c    ] = pack_hilo(kf[i].x, kf[i].y, lo);
                Klo[krow*KPITCH + c    ] = lo;
                Khi[krow*KPITCH + c + 1] = pack_hilo(kf[i].z, kf[i].w, lo);
                Klo[krow*KPITCH + c + 1] = lo;
            }
            #pragma unroll
            for (int i = 0; i < 4; i++) {
                const float* pa = (const float*)&va[i];
                const float* pb = (const float*)&vb[i];
                #pragma unroll
                for (int e = 0; e < 4; e++) {
                    uint32_t lo;
                    Vhi[vkp*VPITCH + vcb + 4*i + e] = pack_hilo(pa[e], pb[e], lo);
                    Vlo[vkp*VPITCH + vcb + 4*i + e] = lo;
                }
            }
            // V batch 1 loads (reuse va/vb regs), then store K batch 1 + V batch 1
            #pragma unroll
            for (int i = 0; i < 4; i++) {
                va[i] = *(const float4*)&Vg[(2*(vkp+32)    )*H_ + vcb + 4*i];
                vb[i] = *(const float4*)&Vg[(2*(vkp+32) + 1)*H_ + vcb + 4*i];
            }
            #pragma unroll
            for (int i = 0; i < 8; i++) {
                const int c = (kcb >> 1) + 2*i;
                uint32_t lo;
                Khi[(krow+64)*KPITCH + c    ] = pack_hilo(kf2[i].x, kf2[i].y, lo);
                Klo[(krow+64)*KPITCH + c    ] = lo;
                Khi[(krow+64)*KPITCH + c + 1] = pack_hilo(kf2[i].z, kf2[i].w, lo);
                Klo[(krow+64)*KPITCH + c + 1] = lo;
            }
            #pragma unroll
            for (int i = 0; i < 4; i++) {
                const float* pa = (const float*)&va[i];
                const float* pb = (const float*)&vb[i];
                #pragma unroll
                for (int e = 0; e < 4; e++) {
                    uint32_t lo;
                    Vhi[(vkp+32)*VPITCH + vcb + 4*i + e] = pack_hilo(pa[e], pb[e], lo);
                    Vlo[(vkp+32)*VPITCH + vcb + 4*i + e] = lo;
                }
            }
            BAR_SYNC(g+1);

            // ---- S = Q @ K^T : 4 ksteps x 16 ntiles x 3 MMAs ----
            float s[16][4] = {};
            #pragma unroll
            for (int ks = 0; ks < 4; ks++) {
                #pragma unroll
                for (int nt = 0; nt < 16; nt++) {
                    const int kr = (nt*8 + gid)*KPITCH + ks*8 + tig;
                    uint32_t bh[2] = { Khi[kr], Khi[kr + 4] };
                    uint32_t bl[2] = { Klo[kr], Klo[kr + 4] };
                    mma_bf16(s[nt], qh[ks], bh);
                    mma_bf16(s[nt], qh[ks], bl);
                    mma_bf16(s[nt], ql[ks], bh);
                }
            }

            // ---- causal mask (tile containing/beyond the diagonal) ----
            if (t == tmax) {
                const int kb = t*128 - qtile*64;   // 0 (even qtile) or -64 (odd)
                #pragma unroll
                for (int nt = 0; nt < 16; nt++) {
                    const int c0 = nt*8 + 2*tig + kb;
                    if (c0     > w16 + gid    ) s[nt][0] = -1e30f;
                    if (c0 + 1 > w16 + gid    ) s[nt][1] = -1e30f;
                    if (c0     > w16 + gid + 8) s[nt][2] = -1e30f;
                    if (c0 + 1 > w16 + gid + 8) s[nt][3] = -1e30f;
                }
            }

            // ---- softmax max (rows gid, gid+8; quad reduce) ----
            float mx0 = -1e30f, mx1 = -1e30f;
            #pragma unroll
            for (int nt = 0; nt < 16; nt++) {
                mx0 = fmaxf(mx0, fmaxf(s[nt][0], s[nt][1]));
                mx1 = fmaxf(mx1, fmaxf(s[nt][2], s[nt][3]));
            }
            mx0 = fmaxf(mx0, __shfl_xor_sync(0xffffffffu, mx0, 1));
            mx0 = fmaxf(mx0, __shfl_xor_sync(0xffffffffu, mx0, 2));
            mx1 = fmaxf(mx1, __shfl_xor_sync(0xffffffffu, mx1, 1));
            mx1 = fmaxf(mx1, __shfl_xor_sync(0xffffffffu, mx1, 2));
            const float mn0 = fmaxf(mst[0], mx0);
            const float mn1 = fmaxf(mst[1], mx1);
            const float sc0 = __expf(mst[0] - mn0);
            const float sc1 = __expf(mst[1] - mn1);
            #pragma unroll
            for (int nt = 0; nt < 8; nt++) {
                o[nt][0] *= sc0; o[nt][1] *= sc0;
                o[nt][2] *= sc1; o[nt][3] *= sc1;
            }

            // ---- interleaved exp/pack + PV per k16-step ----
            float sum0 = 0.0f, sum1 = 0.0f;
            #pragma unroll
            for (int ks = 0; ks < 8; ks++) {
                uint32_t ph[4], pl[4];
                {
                    const int nt = 2*ks;
                    float p0 = __expf(s[nt][0] - mn0);
                    float p1 = __expf(s[nt][1] - mn0);
                    float p2 = __expf(s[nt][2] - mn1);
                    float p3 = __expf(s[nt][3] - mn1);
                    sum0 += p0 + p1;  sum1 += p2 + p3;
                    ph[0] = pack_hilo(p0, p1, pl[0]);
                    ph[1] = pack_hilo(p2, p3, pl[1]);
                }
                {
                    const int nt = 2*ks + 1;
                    float p0 = __expf(s[nt][0] - mn0);
                    float p1 = __expf(s[nt][1] - mn0);
                    float p2 = __expf(s[nt][2] - mn1);
                    float p3 = __expf(s[nt][3] - mn1);
                    sum0 += p0 + p1;  sum1 += p2 + p3;
                    ph[2] = pack_hilo(p0, p1, pl[2]);
                    ph[3] = pack_hilo(p2, p3, pl[3]);
                }
                #pragma unroll
                for (int nt = 0; nt < 8; nt++) {
                    const int v0 = (ks*8 + tig)*VPITCH + nt*8 + gid;
                    const int v1 = v0 + 4*VPITCH;
                    uint32_t vh[2] = { Vhi[v0], Vhi[v1] };
                    uint32_t vl[2] = { Vlo[v0], Vlo[v1] };
                    mma_bf16(o[nt], ph, vh);
                    mma_bf16(o[nt], ph, vl);
                    mma_bf16(o[nt], pl, vh);
                }
            }
            sum0 += __shfl_xor_sync(0xffffffffu, sum0, 1);
            sum0 += __shfl_xor_sync(0xffffffffu, sum0, 2);
            sum1 += __shfl_xor_sync(0xffffffffu, sum1, 1);
            sum1 += __shfl_xor_sync(0xffffffffu, sum1, 2);
            lst[0] = lst[0]*sc0 + sum0;  mst[0] = mn0;
            lst[1] = lst[1]*sc1 + sum1;  mst[1] = mn1;
        }

        // ---- merge the two groups' partial softmax states ----
        if (g == 1) {
            #pragma unroll
            for (int nt = 0; nt < 8; nt++) {
                const int c0 = nt*8 + 2*tig;
                *(float2*)&Osm[(w16 + gid    )*66 + c0] = make_float2(o[nt][0], o[nt][1]);
                *(float2*)&Osm[(w16 + gid + 8)*66 + c0] = make_float2(o[nt][2], o[nt][3]);
            }
            Mm[w16 + gid    ] = mst[0];  Lm[w16 + gid    ] = lst[0];
            Mm[w16 + gid + 8] = mst[1];  Lm[w16 + gid + 8] = lst[1];
        }
        __syncthreads();
        if (g == 0) {
            const float m1a = Mm[w16 + gid    ], l1a = Lm[w16 + gid    ];
            const float m1b = Mm[w16 + gid + 8], l1b = Lm[w16 + gid + 8];
            const float mF0 = fmaxf(mst[0], m1a);
            const float mF1 = fmaxf(mst[1], m1b);
            const float a00 = __expf(mst[0] - mF0), a01 = __expf(m1a - mF0);
            const float a10 = __expf(mst[1] - mF1), a11 = __expf(m1b - mF1);
            const float inv0 = 1.0f / (lst[0]*a00 + l1a*a01);
            const float inv1 = 1.0f / (lst[1]*a10 + l1b*a11);
            const size_t r0 = (size_t)(b*T_ + qtile*64 + w16 + gid);
            #pragma unroll
            for (int nt = 0; nt < 8; nt++) {
                const int c0 = nt*8 + 2*tig;
                float2 u0 = *(const float2*)&Osm[(w16 + gid    )*66 + c0];
                float2 u1 = *(const float2*)&Osm[(w16 + gid + 8)*66 + c0];
                *(float2*)&out[ r0      * H_ + c0] =
                    make_float2((o[nt][0]*a00 + u0.x*a01)*inv0,
                                (o[nt][1]*a00 + u0.y*a01)*inv0);
                *(float2*)&out[(r0 + 8) * H_ + c0] =
                    make_float2((o[nt][2]*a10 + u1.x*a11)*inv1,
                                (o[nt][3]*a10 + u1.y*a11)*inv1);
            }
        }
        __syncthreads();   // merge reads done before next pick reuses buffers
    }
}

// ---------------------------------------------------------------------------
extern "C" void kernel_launch(void* const* d_in, const int* in_sizes, int n_in,
                              void* d_out, int out_size)
{
    const float* x  = (const float*)d_in[0];
    const float* Wk = (const float*)d_in[1];
    const float* Wq = (const float*)d_in[2];
    const float* Wv = (const float*)d_in[3];
    float* out = (float*)d_out;

    const int smem_qkv  = (2*128*QP + 2*64*QP) * (int)sizeof(uint32_t);  // 30720 B
    const int smem_attn = 2 * GWORDS * (int)sizeof(uint32_t);            // 147456 B
    cudaFuncSetAttribute(qkv_mma_kernel, cudaFuncAttributeMaxDynamicSharedMemorySize,
                         smem_qkv);
    cudaFuncSetAttribute(attn_mma_kernel, cudaFuncAttributeMaxDynamicSharedMemorySize,
                         smem_attn);

    qkv_mma_kernel<<<dim3(BT_/128, 3), 128, smem_qkv>>>(x, Wk, Wq, Wv);
    attn_mma_kernel<<<dim3(NQT/2, B_), 256, smem_attn>>>(out);
}

// round 16
// speedup vs baseline: 1.8519x; 1.1831x over previous
#include <cuda_runtime.h>
#include <cuda_bf16.h>
#include <cstdint>

#define B_ 8
#define T_ 2048
#define C_ 768
#define H_ 64
#define BT_ (B_*T_)
#define NQT 32           // number of 64-query tiles per batch

// Packed bf16x2 hi/lo scratch (device globals — no allocation).
// Q/K: [BT][32] words; word w of row m = (X[m][2w], X[m][2w+1]).
// V (key-pair transposed): [BT/2][64]; word at [p][h] = (V[2p][h], V[2p+1][h]).
__device__ uint32_t g_Qph[BT_*32], g_Qpl[BT_*32];
__device__ uint32_t g_Kph[BT_*32], g_Kpl[BT_*32];
__device__ uint32_t g_Vph[(BT_/2)*64], g_Vpl[(BT_/2)*64];

// ---------------------------------------------------------------------------
// helpers
// ---------------------------------------------------------------------------
__device__ __forceinline__ void mma_bf16(float* d, const uint32_t* a, const uint32_t* b) {
    asm volatile(
        "mma.sync.aligned.m16n8k16.row.col.f32.bf16.bf16.f32 "
        "{%0,%1,%2,%3}, {%4,%5,%6,%7}, {%8,%9}, {%0,%1,%2,%3};"
        : "+f"(d[0]), "+f"(d[1]), "+f"(d[2]), "+f"(d[3])
        : "r"(a[0]), "r"(a[1]), "r"(a[2]), "r"(a[3]), "r"(b[0]), "r"(b[1]));
}

// pack (a,b) into bf16x2 (a in low half); residues packed into lo.
__device__ __forceinline__ uint32_t pack_hilo(float a, float b, uint32_t& lo) {
    __nv_bfloat162 h = __floats2bfloat162_rn(a, b);
    float ha = __bfloat162float(h.x), hb = __bfloat162float(h.y);
    __nv_bfloat162 l = __floats2bfloat162_rn(a - ha, b - hb);
    lo = *reinterpret_cast<uint32_t*>(&l);
    return *reinterpret_cast<uint32_t*>(&h);
}

__device__ __forceinline__ void cp16(uint32_t dst_smem, const void* src) {
    asm volatile("cp.async.cg.shared.global [%0], [%1], 16;"
                 :: "r"(dst_smem), "l"(src));
}
#define CP_COMMIT() asm volatile("cp.async.commit_group;")
#define CP_WAIT0()  asm volatile("cp.async.wait_group 0;" ::: "memory")

// ---------------------------------------------------------------------------
// QKV projection — bf16 m16n8k16 hi/lo split (R12 mainloop, packed epilogue).
// out[m,h] = sum_c x[m,c] * W[h,c].  M=16384, N=64, K=768.
// Epilogue writes PRE-PACKED bf16x2 hi/lo in attention's consumption layouts.
// ---------------------------------------------------------------------------
#define KCH 32
#define QP 20

__global__ __launch_bounds__(128) void qkv_mma_kernel(
    const float* __restrict__ x, const float* __restrict__ Wk,
    const float* __restrict__ Wq, const float* __restrict__ Wv)
{
    extern __shared__ uint32_t qsm[];
    uint32_t* Ahi = qsm;                  // 128*20
    uint32_t* Alo = Ahi + 128*QP;         // 128*20
    uint32_t* Bhi = Alo + 128*QP;         // 64*20
    uint32_t* Blo = Bhi + 64*QP;          // 64*20

    const float* W;
    if (blockIdx.y == 0)      W = Wk;
    else if (blockIdx.y == 1) W = Wq;
    else                      W = Wv;

    const int tid  = threadIdx.x;
    const int wid  = tid >> 5;
    const int lane = tid & 31;
    const int gid  = lane >> 2;
    const int tig  = lane & 3;
    const int m0   = blockIdx.x * 128;

    const int lrow = tid >> 3;            // 0..15
    const int lcol = (tid & 7) << 2;      // 0,4,...,28
    const int pcol = lcol >> 1;

    float d[2][8][4] = {};

    for (int kc0 = 0; kc0 < C_; kc0 += KCH) {
        float4 xa[8], wa[4];
        #pragma unroll
        for (int i = 0; i < 8; i++)
            xa[i] = *(const float4*)&x[(size_t)(m0 + lrow + 16*i) * C_ + kc0 + lcol];
        #pragma unroll
        for (int i = 0; i < 4; i++)
            wa[i] = *(const float4*)&W[(size_t)(lrow + 16*i) * C_ + kc0 + lcol];

        __syncthreads();

        #pragma unroll
        for (int i = 0; i < 8; i++) {
            const int base = (lrow + 16*i) * QP + pcol;
            uint32_t lo;
            Ahi[base    ] = pack_hilo(xa[i].x, xa[i].y, lo);  Alo[base    ] = lo;
            Ahi[base + 1] = pack_hilo(xa[i].z, xa[i].w, lo);  Alo[base + 1] = lo;
        }
        #pragma unroll
        for (int i = 0; i < 4; i++) {
            const int base = (lrow + 16*i) * QP + pcol;
            uint32_t lo;
            Bhi[base    ] = pack_hilo(wa[i].x, wa[i].y, lo);  Blo[base    ] = lo;
            Bhi[base + 1] = pack_hilo(wa[i].z, wa[i].w, lo);  Blo[base + 1] = lo;
        }
        __syncthreads();

        #pragma unroll
        for (int ks = 0; ks < 2; ks++) {
            const int cb = ks * 8;

            uint32_t ah[2][4], al[2][4];
            #pragma unroll
            for (int mt = 0; mt < 2; mt++) {
                const int rw = wid*32 + mt*16;
                ah[mt][0] = Ahi[(rw + gid    )*QP + cb + tig    ];
                ah[mt][1] = Ahi[(rw + gid + 8)*QP + cb + tig    ];
                ah[mt][2] = Ahi[(rw + gid    )*QP + cb + tig + 4];
                ah[mt][3] = Ahi[(rw + gid + 8)*QP + cb + tig + 4];
                al[mt][0] = Alo[(rw + gid    )*QP + cb + tig    ];
                al[mt][1] = Alo[(rw + gid + 8)*QP + cb + tig    ];
                al[mt][2] = Alo[(rw + gid    )*QP + cb + tig + 4];
                al[mt][3] = Alo[(rw + gid + 8)*QP + cb + tig + 4];
            }

            uint32_t bh[8][2], bl[8][2];
            #pragma unroll
            for (int nt = 0; nt < 8; nt++) {
                bh[nt][0] = Bhi[(nt*8 + gid)*QP + cb + tig    ];
                bh[nt][1] = Bhi[(nt*8 + gid)*QP + cb + tig + 4];
                bl[nt][0] = Blo[(nt*8 + gid)*QP + cb + tig    ];
                bl[nt][1] = Blo[(nt*8 + gid)*QP + cb + tig + 4];
            }

            #pragma unroll
            for (int mt = 0; mt < 2; mt++)
                #pragma unroll
                for (int nt = 0; nt < 8; nt++) {
                    mma_bf16(d[mt][nt], ah[mt], bh[nt]);
                    mma_bf16(d[mt][nt], ah[mt], bl[nt]);
                    mma_bf16(d[mt][nt], al[mt], bh[nt]);
                }
        }
    }

    // ---- epilogue: write pre-packed hi/lo in attention layouts ----
    if (blockIdx.y != 2) {
        // K (y=0) / Q (y=1): row-major packed pairs [BT][32].
        uint32_t* Ohi = (blockIdx.y == 0) ? g_Kph : g_Qph;
        uint32_t* Olo = (blockIdx.y == 0) ? g_Kpl : g_Qpl;
        #pragma unroll
        for (int mt = 0; mt < 2; mt++) {
            const int r0 = m0 + wid*32 + mt*16 + gid;
            #pragma unroll
            for (int nt = 0; nt < 8; nt++) {
                const int pw = nt*4 + tig;
                uint32_t lo0, lo1;
                uint32_t h0 = pack_hilo(d[mt][nt][0], d[mt][nt][1], lo0);
                uint32_t h1 = pack_hilo(d[mt][nt][2], d[mt][nt][3], lo1);
                Ohi[(size_t)r0      * 32 + pw] = h0;  Olo[(size_t)r0      * 32 + pw] = lo0;
                Ohi[(size_t)(r0+8) * 32 + pw] = h1;  Olo[(size_t)(r0+8) * 32 + pw] = lo1;
            }
        }
    } else {
        // V: key-pair transposed [BT/2][64]. Pair rows (2j,2j+1) via shfl_xor 4
        // (partner = gid^1, same tig). Even-gid lanes store.
        #pragma unroll
        for (int mt = 0; mt < 2; mt++) {
            const int r0 = m0 + wid*32 + mt*16 + gid;
            #pragma unroll
            for (int nt = 0; nt < 8; nt++) {
                float e0 = __shfl_xor_sync(0xffffffffu, d[mt][nt][0], 4);
                float e1 = __shfl_xor_sync(0xffffffffu, d[mt][nt][1], 4);
                float e2 = __shfl_xor_sync(0xffffffffu, d[mt][nt][2], 4);
                float e3 = __shfl_xor_sync(0xffffffffu, d[mt][nt][3], 4);
                if (!(gid & 1)) {
                    const int c0 = nt*8 + 2*tig;
                    const size_t p0 = (size_t)(r0     ) >> 1;
                    const size_t p1 = (size_t)(r0 + 8) >> 1;
                    uint32_t lo, h;
                    h = pack_hilo(d[mt][nt][0], e0, lo);
                    g_Vph[p0*64 + c0    ] = h;  g_Vpl[p0*64 + c0    ] = lo;
                    h = pack_hilo(d[mt][nt][1], e1, lo);
                    g_Vph[p0*64 + c0 + 1] = h;  g_Vpl[p0*64 + c0 + 1] = lo;
                    h = pack_hilo(d[mt][nt][2], e2, lo);
                    g_Vph[p1*64 + c0    ] = h;  g_Vpl[p1*64 + c0    ] = lo;
                    h = pack_hilo(d[mt][nt][3], e3, lo);
                    g_Vph[p1*64 + c0 + 1] = h;  g_Vpl[p1*64 + c0 + 1] = lo;
                }
            }
        }
    }
}

// ---------------------------------------------------------------------------
// Flash attention — bf16 m16n8k16 hi/lo split, pre-packed K/V/Q, cp.async
// double-buffered staging. Grid (16, 8): CTA (p, b), qtiles {p, 31-p}.
// 256 threads / 8 warps: group g handles kt ≡ g (mod 2), 2 smem buffers.
// Per-buffer layout (words): Khi[64*36] | Klo[64*36] | Vhi[32*72] | Vlo[32*72].
// ---------------------------------------------------------------------------
#define KPITCH 36
#define VPITCH 72
#define GBUF   9216                       // words per buffer
#define KOFF_LO 2304
#define VOFF_HI 4608
#define VOFF_LO 6912

#define BAR_SYNC(id) asm volatile("bar.sync %0, %1;" :: "r"(id), "r"(128) : "memory")

__global__ __launch_bounds__(256) void attn_mma_kernel(float* __restrict__ out)
{
    extern __shared__ uint32_t shb[];

    const int b    = blockIdx.y;
    const int p    = blockIdx.x;
    const int tid  = threadIdx.x;
    const int w    = tid >> 5;
    const int g    = w >> 2;            // warp group 0/1
    const int wg   = w & 3;             // warp within group
    const int lane = tid & 31;
    const int gid  = lane >> 2;
    const int tig  = lane & 3;
    const int w16  = wg * 16;
    const int ltid = tid & 127;

    const uint32_t smb = (uint32_t)__cvta_generic_to_shared(shb);
    const uint32_t grpb = smb + (uint32_t)(g * 2 * GBUF) * 4;   // byte addr

    // Merge region reuses group 1 buffer 0 (dead after kt loop).
    float* Osm = (float*)(shb + 2*GBUF);   // 64 x 66 = 4224 (< 9216)
    float* Mm  = Osm + 64*66;              // 64
    float* Lm  = Mm + 64;                  // 64

    // copy-assignment indices (constant per thread)
    // K: idx = ltid + 128*i -> row = idx>>3 (0..63), c4 = (idx&7)*4
    // V: idx = ltid + 128*i -> vp = idx>>4 (0..31), c4 = (idx&15)*4

    auto issue_cp = [&](int kt, int bufv) {
        const size_t kb = (size_t)(b*T_ + kt*64);
        const size_t vb = (size_t)(b*(T_/2) + kt*32);
        const uint32_t base = grpb + (uint32_t)(bufv * GBUF) * 4;
        #pragma unroll
        for (int i = 0; i < 4; i++) {
            const int idx = ltid + 128*i;
            const int row = idx >> 3, c4 = (idx & 7) * 4;
            cp16(base + (uint32_t)(row*KPITCH + c4)*4,           g_Kph + (kb+row)*32 + c4);
            cp16(base + (uint32_t)(KOFF_LO + row*KPITCH + c4)*4, g_Kpl + (kb+row)*32 + c4);
        }
        #pragma unroll
        for (int i = 0; i < 4; i++) {
            const int idx = ltid + 128*i;
            const int vp = idx >> 4, c4 = (idx & 15) * 4;
            cp16(base + (uint32_t)(VOFF_HI + vp*VPITCH + c4)*4,  g_Vph + (vb+vp)*64 + c4);
            cp16(base + (uint32_t)(VOFF_LO + vp*VPITCH + c4)*4,  g_Vpl + (vb+vp)*64 + c4);
        }
        CP_COMMIT();
    };

    for (int pick = 0; pick < 2; pick++) {
        const int qtile = pick ? (NQT - 1 - p) : p;

        // ---- Q A-fragments straight from pre-packed gmem ----
        const uint32_t* Qhp = g_Qph + (size_t)(b*T_ + qtile*64 + w16) * 32;
        const uint32_t* Qlp = g_Qpl + (size_t)(b*T_ + qtile*64 + w16) * 32;
        uint32_t qh[4][4], ql[4][4];
        #pragma unroll
        for (int ks = 0; ks < 4; ks++) {
            const int wbase = ks*8 + tig;
            qh[ks][0] = Qhp[ gid     *32 + wbase    ];
            qh[ks][1] = Qhp[(gid + 8)*32 + wbase    ];
            qh[ks][2] = Qhp[ gid     *32 + wbase + 4];
            qh[ks][3] = Qhp[(gid + 8)*32 + wbase + 4];
            ql[ks][0] = Qlp[ gid     *32 + wbase    ];
            ql[ks][1] = Qlp[(gid + 8)*32 + wbase    ];
            ql[ks][2] = Qlp[ gid     *32 + wbase + 4];
            ql[ks][3] = Qlp[(gid + 8)*32 + wbase + 4];
        }

        float o[8][4] = {};
        float mst[2] = {-1e30f, -1e30f};
        float lst[2] = {0.0f, 0.0f};

        int buf = 0;
        if (g <= qtile) issue_cp(g, 0);    // prologue prefetch

        for (int kt = g; kt <= qtile; kt += 2) {
            CP_WAIT0();
            BAR_SYNC(g+1);                  // group's copies visible; prev compute done
            if (kt + 2 <= qtile) issue_cp(kt + 2, buf ^ 1);

            const uint32_t* Khi = shb + g*2*GBUF + buf*GBUF;
            const uint32_t* Klo = Khi + KOFF_LO;
            const uint32_t* Vhi = Khi + VOFF_HI;
            const uint32_t* Vlo = Khi + VOFF_LO;

            // ---- S = Q @ K^T : 4 ksteps x 8 ntiles x 3 MMAs ----
            float s[8][4] = {};
            #pragma unroll
            for (int ks = 0; ks < 4; ks++) {
                #pragma unroll
                for (int nt = 0; nt < 8; nt++) {
                    const int kr = (nt*8 + gid)*KPITCH + ks*8 + tig;
                    uint32_t bh[2] = { Khi[kr], Khi[kr + 4] };
                    uint32_t bl[2] = { Klo[kr], Klo[kr + 4] };
                    mma_bf16(s[nt], qh[ks], bh);
                    mma_bf16(s[nt], qh[ks], bl);
                    mma_bf16(s[nt], ql[ks], bh);
                }
            }

            // ---- causal mask (diagonal tile only) ----
            if (kt == qtile) {
                #pragma unroll
                for (int nt = 0; nt < 8; nt++) {
                    const int c0 = nt*8 + 2*tig;
                    if (c0     > w16 + gid    ) s[nt][0] = -1e30f;
                    if (c0 + 1 > w16 + gid    ) s[nt][1] = -1e30f;
                    if (c0     > w16 + gid + 8) s[nt][2] = -1e30f;
                    if (c0 + 1 > w16 + gid + 8) s[nt][3] = -1e30f;
                }
            }

            // ---- warp-local online softmax; P packed to bf16 A-frags ----
            float mx0 = -1e30f, mx1 = -1e30f;
            #pragma unroll
            for (int nt = 0; nt < 8; nt++) {
                mx0 = fmaxf(mx0, fmaxf(s[nt][0], s[nt][1]));
                mx1 = fmaxf(mx1, fmaxf(s[nt][2], s[nt][3]));
            }
            mx0 = fmaxf(mx0, __shfl_xor_sync(0xffffffffu, mx0, 1));
            mx0 = fmaxf(mx0, __shfl_xor_sync(0xffffffffu, mx0, 2));
            mx1 = fmaxf(mx1, __shfl_xor_sync(0xffffffffu, mx1, 1));
            mx1 = fmaxf(mx1, __shfl_xor_sync(0xffffffffu, mx1, 2));
            const float mn0 = fmaxf(mst[0], mx0);
            const float mn1 = fmaxf(mst[1], mx1);
            const float sc0 = __expf(mst[0] - mn0);
            const float sc1 = __expf(mst[1] - mn1);

            float sum0 = 0.0f, sum1 = 0.0f;
            uint32_t ph[16], plr[16];
            #pragma unroll
            for (int nt = 0; nt < 8; nt++) {
                float p0 = __expf(s[nt][0] - mn0);
                float p1 = __expf(s[nt][1] - mn0);
                float p2 = __expf(s[nt][2] - mn1);
                float p3 = __expf(s[nt][3] - mn1);
                sum0 += p0 + p1;
                sum1 += p2 + p3;
                ph[2*nt    ] = pack_hilo(p0, p1, plr[2*nt    ]);
                ph[2*nt + 1] = pack_hilo(p2, p3, plr[2*nt + 1]);
            }
            sum0 += __shfl_xor_sync(0xffffffffu, sum0, 1);
            sum0 += __shfl_xor_sync(0xffffffffu, sum0, 2);
            sum1 += __shfl_xor_sync(0xffffffffu, sum1, 1);
            sum1 += __shfl_xor_sync(0xffffffffu, sum1, 2);
            lst[0] = lst[0]*sc0 + sum0;  mst[0] = mn0;
            lst[1] = lst[1]*sc1 + sum1;  mst[1] = mn1;
            #pragma unroll
            for (int nt = 0; nt < 8; nt++) {
                o[nt][0] *= sc0; o[nt][1] *= sc0;
                o[nt][2] *= sc1; o[nt][3] *= sc1;
            }

            // ---- O += P @ V ----
            #pragma unroll
            for (int ks = 0; ks < 4; ks++) {
                #pragma unroll
                for (int nt = 0; nt < 8; nt++) {
                    const int v0 = (ks*8 + tig)*VPITCH + nt*8 + gid;
                    const int v1 = v0 + 4*VPITCH;
                    uint32_t vh[2] = { Vhi[v0], Vhi[v1] };
                    uint32_t vl[2] = { Vlo[v0], Vlo[v1] };
                    mma_bf16(o[nt], &ph[4*ks],  vh);
                    mma_bf16(o[nt], &ph[4*ks],  vl);
                    mma_bf16(o[nt], &plr[4*ks], vh);
                }
            }
            buf ^= 1;
        }

        // ---- merge the two groups' partial softmax states ----
        if (g == 1) {
            #pragma unroll
            for (int nt = 0; nt < 8; nt++) {
                const int c0 = nt*8 + 2*tig;
                *(float2*)&Osm[(w16 + gid    )*66 + c0] = make_float2(o[nt][0], o[nt][1]);
                *(float2*)&Osm[(w16 + gid + 8)*66 + c0] = make_float2(o[nt][2], o[nt][3]);
            }
            Mm[w16 + gid    ] = mst[0];  Lm[w16 + gid    ] = lst[0];
            Mm[w16 + gid + 8] = mst[1];  Lm[w16 + gid + 8] = lst[1];
        }
        __syncthreads();
        if (g == 0) {
            const float m1a = Mm[w16 + gid    ], l1a = Lm[w16 + gid    ];
            const float m1b = Mm[w16 + gid + 8], l1b = Lm[w16 + gid + 8];
            const float mF0 = fmaxf(mst[0], m1a);
            const float mF1 = fmaxf(mst[1], m1b);
            const float a00 = __expf(mst[0] - mF0), a01 = __expf(m1a - mF0);
            const float a10 = __expf(mst[1] - mF1), a11 = __expf(m1b - mF1);
            const float inv0 = 1.0f / (lst[0]*a00 + l1a*a01);
            const float inv1 = 1.0f / (lst[1]*a10 + l1b*a11);
            const size_t r0 = (size_t)(b*T_ + qtile*64 + w16 + gid);
            #pragma unroll
            for (int nt = 0; nt < 8; nt++) {
                const int c0 = nt*8 + 2*tig;
                float2 u0 = *(const float2*)&Osm[(w16 + gid    )*66 + c0];
                float2 u1 = *(const float2*)&Osm[(w16 + gid + 8)*66 + c0];
                *(float2*)&out[ r0      * H_ + c0] =
                    make_float2((o[nt][0]*a00 + u0.x*a01)*inv0,
                                (o[nt][1]*a00 + u0.y*a01)*inv0);
                *(float2*)&out[(r0 + 8) * H_ + c0] =
                    make_float2((o[nt][2]*a10 + u1.x*a11)*inv1,
                                (o[nt][3]*a10 + u1.y*a11)*inv1);
            }
        }
        __syncthreads();   // merge reads done before next pick reuses buffers
    }
}

// ---------------------------------------------------------------------------
extern "C" void kernel_launch(void* const* d_in, const int* in_sizes, int n_in,
                              void* d_out, int out_size)
{
    const float* x  = (const float*)d_in[0];
    const float* Wk = (const float*)d_in[1];
    const float* Wq = (const float*)d_in[2];
    const float* Wv = (const float*)d_in[3];
    float* out = (float*)d_out;

    const int smem_qkv  = (2*128*QP + 2*64*QP) * (int)sizeof(uint32_t);  // 30720 B
    const int smem_attn = 4 * GBUF * (int)sizeof(uint32_t);              // 147456 B
    cudaFuncSetAttribute(qkv_mma_kernel, cudaFuncAttributeMaxDynamicSharedMemorySize,
                         smem_qkv);
    cudaFuncSetAttribute(attn_mma_kernel, cudaFuncAttributeMaxDynamicSharedMemorySize,
                         smem_attn);

    qkv_mma_kernel<<<dim3(BT_/128, 3), 128, smem_qkv>>>(x, Wk, Wq, Wv);
    attn_mma_kernel<<<dim3(NQT/2, B_), 256, smem_attn>>>(out);
}